// round 1
// baseline (speedup 1.0000x reference)
#include <cuda_runtime.h>
#include <math.h>

#define BS   16384
#define NC   2000
#define NPAD 2048
#define D    512
#define TM   64
#define TN   128
#define KB   16

// scratch (device globals: allocation-free)
__device__ float g_finv[BS];
__device__ float g_winv[NC];
__device__ float g_ta[BS];     // -0.95*tgt - 0.01*aux_sum  per row
__device__ float g_lse[BS];
__device__ float g_corr[BS];

// ---------------------------------------------------------------------------
// inverse L2 norm per row (len 512). which==0 -> g_finv, which==1 -> g_winv
// ---------------------------------------------------------------------------
__global__ void rownorm_kernel(const float* __restrict__ x, int which) {
    int row = blockIdx.x;
    const float4* p = reinterpret_cast<const float4*>(x + (size_t)row * D);
    float4 v = p[threadIdx.x];                       // 128 threads * 4 = 512
    float s = v.x * v.x + v.y * v.y + v.z * v.z + v.w * v.w;
    #pragma unroll
    for (int o = 16; o > 0; o >>= 1) s += __shfl_xor_sync(0xffffffffu, s, o);
    __shared__ float sm[4];
    int warp = threadIdx.x >> 5;
    if ((threadIdx.x & 31) == 0) sm[warp] = s;
    __syncthreads();
    if (threadIdx.x == 0) {
        float t = sm[0] + sm[1] + sm[2] + sm[3];
        float inv = 1.0f / fmaxf(sqrtf(t), 1e-12f);
        if (which == 0) g_finv[row] = inv;
        else            g_winv[row] = inv;
    }
}

// ---------------------------------------------------------------------------
// per-row gathers: tgt = pred[i,label[i]], aux_sum = sum_j pred[i,aux[i,j]]
// 6 warps per row, one dot product each.  g_ta = -0.95*tgt - 0.01*aux_sum
// ---------------------------------------------------------------------------
__global__ void gather_kernel(const float* __restrict__ f, const float* __restrict__ w,
                              const int* __restrict__ label, const int* __restrict__ aux) {
    int row  = blockIdx.x;
    int warp = threadIdx.x >> 5;
    int lane = threadIdx.x & 31;
    int cls  = (warp == 0) ? label[row] : aux[row * 5 + warp - 1];
    const float4* fr = reinterpret_cast<const float4*>(f + (size_t)row * D);
    const float4* wr = reinterpret_cast<const float4*>(w + (size_t)cls * D);
    float s = 0.0f;
    #pragma unroll
    for (int k = lane; k < D / 4; k += 32) {
        float4 a = fr[k], b = wr[k];
        s += a.x * b.x + a.y * b.y + a.z * b.z + a.w * b.w;
    }
    #pragma unroll
    for (int o = 16; o > 0; o >>= 1) s += __shfl_xor_sync(0xffffffffu, s, o);
    __shared__ float sm[6];
    if (lane == 0) sm[warp] = s * g_finv[row] * g_winv[cls] * 20.0f;  // 1/TEMP = 20
    __syncthreads();
    if (threadIdx.x == 0) {
        float tgt  = sm[0];
        float auxs = sm[1] + sm[2] + sm[3] + sm[4] + sm[5];
        // 0.5*[(-tgt+lse) + (-(1-a)tgt + lse - (a/5)*auxs)] = lse - 0.95*tgt - 0.01*auxs
        g_ta[row] = -0.95f * tgt - 0.01f * auxs;
    }
}

// ---------------------------------------------------------------------------
// fused GEMM + online softmax-reduction.
// Block: TM=64 rows x all 2048 (padded) classes in TN=128 chunks.
// 256 threads, each a 4x8 micro-tile.  Per chunk: full-K accumulate,
// then online (max, sumexp, argmax) update.  Cross-thread combine at end.
// ---------------------------------------------------------------------------
__global__ void __launch_bounds__(256)
fused_kernel(const float* __restrict__ f, const float* __restrict__ w,
             const int* __restrict__ label) {
    __shared__ float As[KB][TM];        // 4 KB
    __shared__ float Bs[KB][TN];        // 8 KB
    __shared__ float redM[TM][17];
    __shared__ float redS[TM][17];
    __shared__ int   redI[TM][17];

    const int tid   = threadIdx.x;
    const int tx    = tid & 15;         // column group (8 cols)
    const int ty    = tid >> 4;         // row group (4 rows)
    const int rbase = ty * 4;
    const int cbase = tx * 8;
    const int browBase = blockIdx.x * TM;

    // loader mapping: 4 threads per row, float4 each
    const int arow = tid >> 2;          // 0..63
    const int akv  = (tid & 3) * 4;     // k offset within KB
    const float* aptr  = f + (size_t)(browBase + arow) * D + akv;
    const float  aScale = g_finv[browBase + arow] * 20.0f;

    float m[4], ssum[4];
    int   idx[4];
    #pragma unroll
    for (int ii = 0; ii < 4; ++ii) { m[ii] = -INFINITY; ssum[ii] = 0.0f; idx[ii] = -1; }

    for (int nb = 0; nb < NPAD / TN; ++nb) {
        // classes this thread loads for B (2 of them)
        const int c0 = nb * TN + arow;
        const int c1 = c0 + 64;
        const float sB0 = (c0 < NC) ? g_winv[c0] : 0.0f;
        const float sB1 = (c1 < NC) ? g_winv[c1] : 0.0f;
        const float* bp0 = w + (size_t)(c0 < NC ? c0 : 0) * D + akv;
        const float* bp1 = w + (size_t)(c1 < NC ? c1 : 0) * D + akv;

        float acc[4][8];
        #pragma unroll
        for (int ii = 0; ii < 4; ++ii)
            #pragma unroll
            for (int jj = 0; jj < 8; ++jj) acc[ii][jj] = 0.0f;

        for (int kb = 0; kb < D; kb += KB) {
            float4 av  = *reinterpret_cast<const float4*>(aptr + kb);
            float4 bv0 = *reinterpret_cast<const float4*>(bp0 + kb);
            float4 bv1 = *reinterpret_cast<const float4*>(bp1 + kb);
            __syncthreads();   // previous iteration done reading smem
            As[akv + 0][arow] = av.x * aScale;
            As[akv + 1][arow] = av.y * aScale;
            As[akv + 2][arow] = av.z * aScale;
            As[akv + 3][arow] = av.w * aScale;
            Bs[akv + 0][arow]      = bv0.x * sB0;
            Bs[akv + 1][arow]      = bv0.y * sB0;
            Bs[akv + 2][arow]      = bv0.z * sB0;
            Bs[akv + 3][arow]      = bv0.w * sB0;
            Bs[akv + 0][arow + 64] = bv1.x * sB1;
            Bs[akv + 1][arow + 64] = bv1.y * sB1;
            Bs[akv + 2][arow + 64] = bv1.z * sB1;
            Bs[akv + 3][arow + 64] = bv1.w * sB1;
            __syncthreads();
            #pragma unroll
            for (int k = 0; k < KB; ++k) {
                float4 a  = *reinterpret_cast<const float4*>(&As[k][rbase]);
                float4 b0 = *reinterpret_cast<const float4*>(&Bs[k][cbase]);
                float4 b1 = *reinterpret_cast<const float4*>(&Bs[k][cbase + 4]);
                float ra[4] = {a.x, a.y, a.z, a.w};
                float rb[8] = {b0.x, b0.y, b0.z, b0.w, b1.x, b1.y, b1.z, b1.w};
                #pragma unroll
                for (int ii = 0; ii < 4; ++ii)
                    #pragma unroll
                    for (int jj = 0; jj < 8; ++jj)
                        acc[ii][jj] = fmaf(ra[ii], rb[jj], acc[ii][jj]);
            }
        }

        // online (max, sumexp, argmax) update over this chunk's 8 columns
        #pragma unroll
        for (int ii = 0; ii < 4; ++ii) {
            #pragma unroll
            for (int jj = 0; jj < 8; ++jj) {
                int n = nb * TN + cbase + jj;
                if (n < NC) {
                    float v  = acc[ii][jj];
                    float om = m[ii];
                    if (v > om) {
                        ssum[ii] = ssum[ii] * __expf(om - v) + 1.0f;
                        m[ii] = v;
                        idx[ii] = n;
                    } else {
                        ssum[ii] += __expf(v - om);
                    }
                }
            }
        }
    }

    // cross-thread combine: 16 partials (one per tx) per row
    #pragma unroll
    for (int ii = 0; ii < 4; ++ii) {
        redM[rbase + ii][tx] = m[ii];
        redS[rbase + ii][tx] = ssum[ii];
        redI[rbase + ii][tx] = idx[ii];
    }
    __syncthreads();
    if (tid < TM) {
        float bm = -INFINITY, bs = 0.0f;
        int   bi = -1;
        #pragma unroll
        for (int t = 0; t < 16; ++t) {
            float tm = redM[tid][t];
            float ts = redS[tid][t];
            if (tm > bm) {
                bs = bs * __expf(bm - tm) + ts;
                bm = tm;
                bi = redI[tid][t];
            } else {
                bs += ts * __expf(tm - bm);
            }
        }
        int grow = browBase + tid;
        g_lse[grow]  = bm + __logf(bs);
        g_corr[grow] = (bi == label[grow]) ? 1.0f : 0.0f;
    }
}

// ---------------------------------------------------------------------------
// final deterministic reduction: loss = mean(lse + ta), acc = mean(corr)
// ---------------------------------------------------------------------------
__global__ void final_kernel(float* __restrict__ out, int out_size) {
    int tid = threadIdx.x;
    float sl = 0.0f, sc = 0.0f;
    for (int i = tid; i < BS; i += 1024) {
        sl += g_lse[i] + g_ta[i];
        sc += g_corr[i];
    }
    #pragma unroll
    for (int o = 16; o > 0; o >>= 1) {
        sl += __shfl_xor_sync(0xffffffffu, sl, o);
        sc += __shfl_xor_sync(0xffffffffu, sc, o);
    }
    __shared__ float a1[32], a2[32];
    int w = tid >> 5, l = tid & 31;
    if (l == 0) { a1[w] = sl; a2[w] = sc; }
    __syncthreads();
    if (w == 0) {
        sl = a1[l];
        sc = a2[l];
        #pragma unroll
        for (int o = 16; o > 0; o >>= 1) {
            sl += __shfl_xor_sync(0xffffffffu, sl, o);
            sc += __shfl_xor_sync(0xffffffffu, sc, o);
        }
        if (tid == 0) {
            out[0] = sl * (1.0f / BS);
            if (out_size > 1) out[1] = sc * (1.0f / BS);
        }
    }
}

extern "C" void kernel_launch(void* const* d_in, const int* in_sizes, int n_in,
                              void* d_out, int out_size) {
    const float* f     = (const float*)d_in[0];
    const float* w     = (const float*)d_in[1];
    const int*   label = (const int*)d_in[2];
    const int*   aux   = (const int*)d_in[3];
    (void)in_sizes; (void)n_in;

    rownorm_kernel<<<BS, 128>>>(f, 0);
    rownorm_kernel<<<NC, 128>>>(w, 1);
    gather_kernel<<<BS, 192>>>(f, w, label, aux);
    fused_kernel<<<BS / TM, 256>>>(f, w, label);
    final_kernel<<<1, 1024>>>((float*)d_out, out_size);
}

// round 3
// speedup vs baseline: 7.7482x; 7.7482x over previous
#include <cuda_runtime.h>
#include <cuda_bf16.h>
#include <math.h>
#include <stdint.h>

// ---------------------------------------------------------------------------
// problem constants
// ---------------------------------------------------------------------------
#define BS     16384
#define NC     2000
#define NPADC  2048
#define DIM    512
#define TMR    128              // M rows per CTA
#define NCHUNK 128              // classes per N chunk
#define BK     64               // K per smem stage
#define ROWB   144              // padded smem row stride in bytes (72 bf16)
#define ABYTES (128 * ROWB)     // 18432
#define BOFF   ABYTES
#define STAGE  (2 * ABYTES)     // 36864 per stage (A+B)
#define DSMEM  (2 * STAGE)      // 73728 (double buffered)
#define NSTAGES_TOTAL 128       // 16 n-chunks * 8 k-blocks

// ---------------------------------------------------------------------------
// device scratch (allocation-free)
// ---------------------------------------------------------------------------
__device__ float g_finv[BS];
__device__ float g_winv[NC];
__device__ float g_ta[BS];
__device__ float g_lse[BS];
__device__ float g_corr[BS];
__device__ __nv_bfloat16 g_fb[(size_t)BS * DIM];
__device__ __nv_bfloat16 g_wb[(size_t)NPADC * DIM];

// ---------------------------------------------------------------------------
// helpers
// ---------------------------------------------------------------------------
static __device__ __forceinline__ uint32_t sm2u(const void* p) {
    uint32_t a;
    asm("{ .reg .u64 t; cvta.to.shared.u64 t, %1; cvt.u32.u64 %0, t; }"
        : "=r"(a) : "l"(p));
    return a;
}

#define LDSM4(r0, r1, r2, r3, addr) \
    asm volatile("ldmatrix.sync.aligned.m8n8.x4.shared.b16 {%0,%1,%2,%3}, [%4];" \
                 : "=r"(r0), "=r"(r1), "=r"(r2), "=r"(r3) : "r"(addr))

#define MMA16816(d, a, b) \
    asm volatile("mma.sync.aligned.m16n8k16.row.col.f32.bf16.bf16.f32 " \
                 "{%0,%1,%2,%3}, {%4,%5,%6,%7}, {%8,%9}, {%0,%1,%2,%3};" \
                 : "+f"((d)[0]), "+f"((d)[1]), "+f"((d)[2]), "+f"((d)[3]) \
                 : "r"((a)[0]), "r"((a)[1]), "r"((a)[2]), "r"((a)[3]), \
                   "r"((b)[0]), "r"((b)[1]))

#define CPASYNC16(dst, src) \
    asm volatile("cp.async.cg.shared.global [%0], [%1], 16;" :: "r"(dst), "l"(src))

// ---------------------------------------------------------------------------
// prep: rownorm + bf16 convert.  f -> g_fb (scaled by 1/||f||), w -> g_wb
// ---------------------------------------------------------------------------
__global__ void prep_f_kernel(const float* __restrict__ x) {
    int row = blockIdx.x;
    const float4* p = reinterpret_cast<const float4*>(x + (size_t)row * DIM);
    float4 v = p[threadIdx.x];
    float s = v.x * v.x + v.y * v.y + v.z * v.z + v.w * v.w;
    #pragma unroll
    for (int o = 16; o > 0; o >>= 1) s += __shfl_xor_sync(0xffffffffu, s, o);
    __shared__ float sm[4];
    __shared__ float sinv;
    int warp = threadIdx.x >> 5;
    if ((threadIdx.x & 31) == 0) sm[warp] = s;
    __syncthreads();
    if (threadIdx.x == 0) {
        float t = sm[0] + sm[1] + sm[2] + sm[3];
        float inv = 1.0f / fmaxf(sqrtf(t), 1e-12f);
        g_finv[row] = inv;
        sinv = inv;
    }
    __syncthreads();
    float inv = sinv;
    __nv_bfloat162 h0 = __floats2bfloat162_rn(v.x * inv, v.y * inv);
    __nv_bfloat162 h1 = __floats2bfloat162_rn(v.z * inv, v.w * inv);
    __nv_bfloat162* dp = reinterpret_cast<__nv_bfloat162*>(
        g_fb + (size_t)row * DIM + threadIdx.x * 4);
    dp[0] = h0;
    dp[1] = h1;
}

__global__ void prep_w_kernel(const float* __restrict__ x) {
    int row = blockIdx.x;
    __nv_bfloat162* dp = reinterpret_cast<__nv_bfloat162*>(
        g_wb + (size_t)row * DIM + threadIdx.x * 4);
    if (row >= NC) {
        __nv_bfloat162 z = __floats2bfloat162_rn(0.0f, 0.0f);
        dp[0] = z; dp[1] = z;
        return;
    }
    const float4* p = reinterpret_cast<const float4*>(x + (size_t)row * DIM);
    float4 v = p[threadIdx.x];
    float s = v.x * v.x + v.y * v.y + v.z * v.z + v.w * v.w;
    #pragma unroll
    for (int o = 16; o > 0; o >>= 1) s += __shfl_xor_sync(0xffffffffu, s, o);
    __shared__ float sm[4];
    __shared__ float sinv;
    int warp = threadIdx.x >> 5;
    if ((threadIdx.x & 31) == 0) sm[warp] = s;
    __syncthreads();
    if (threadIdx.x == 0) {
        float t = sm[0] + sm[1] + sm[2] + sm[3];
        float inv = 1.0f / fmaxf(sqrtf(t), 1e-12f);
        g_winv[row] = inv;
        sinv = inv;
    }
    __syncthreads();
    float inv = sinv;
    __nv_bfloat162 h0 = __floats2bfloat162_rn(v.x * inv, v.y * inv);
    __nv_bfloat162 h1 = __floats2bfloat162_rn(v.z * inv, v.w * inv);
    dp[0] = h0;
    dp[1] = h1;
}

// ---------------------------------------------------------------------------
// per-row gathers (exact f32): g_ta = -0.95*tgt - 0.01*aux_sum
// ---------------------------------------------------------------------------
__global__ void gather_kernel(const float* __restrict__ f, const float* __restrict__ w,
                              const int* __restrict__ label, const int* __restrict__ aux) {
    int row  = blockIdx.x;
    int warp = threadIdx.x >> 5;
    int lane = threadIdx.x & 31;
    int cls  = (warp == 0) ? label[row] : aux[row * 5 + warp - 1];
    const float4* fr = reinterpret_cast<const float4*>(f + (size_t)row * DIM);
    const float4* wr = reinterpret_cast<const float4*>(w + (size_t)cls * DIM);
    float s = 0.0f;
    #pragma unroll
    for (int k = lane; k < DIM / 4; k += 32) {
        float4 a = fr[k], b = wr[k];
        s += a.x * b.x + a.y * b.y + a.z * b.z + a.w * b.w;
    }
    #pragma unroll
    for (int o = 16; o > 0; o >>= 1) s += __shfl_xor_sync(0xffffffffu, s, o);
    __shared__ float sm[6];
    if (lane == 0) sm[warp] = s * g_finv[row] * g_winv[cls] * 20.0f;
    __syncthreads();
    if (threadIdx.x == 0) {
        float tgt  = sm[0];
        float auxs = sm[1] + sm[2] + sm[3] + sm[4] + sm[5];
        g_ta[row] = -0.95f * tgt - 0.01f * auxs;
    }
}

// ---------------------------------------------------------------------------
// fused bf16 mma.sync GEMM + fixed-max softmax reduction.
// 256 threads = 8 warps in 4(M) x 2(N) grid, warp tile 32x64 (m16n8k16).
// Double-buffered cp.async stages: A[128x64] + B[128x64] bf16, 144B rows.
// ---------------------------------------------------------------------------
__global__ void __launch_bounds__(256, 1)
gemm_fused(const int* __restrict__ label) {
    extern __shared__ char dsm[];
    __shared__ float s_sum[2][128];
    __shared__ float s_max[2][128];
    __shared__ int   s_idx[2][128];

    const int tid   = threadIdx.x;
    const int lane  = tid & 31;
    const int wid   = tid >> 5;
    const int warpM = wid & 3;     // 0..3  -> rows warpM*32
    const int warpN = wid >> 2;    // 0..1  -> cols warpN*64
    const uint32_t sbase = sm2u(dsm);
    const int mBase = blockIdx.x * TMR;

    // loader mapping: thread -> (row mod 32, k8) ; 4 rows per thread
    const int lrow = tid >> 3;
    const int lk8  = tid & 7;
    const __nv_bfloat16* __restrict__ Ag = g_fb + (size_t)mBase * DIM + lk8 * 8;
    const __nv_bfloat16* __restrict__ Bg = g_wb + lk8 * 8;

    // ldmatrix base addresses (stage 0; add st*STAGE + kk*32 per use)
    const uint32_t aAddr = sbase
        + (uint32_t)(warpM * 32 + (lane & 15)) * ROWB + (uint32_t)(lane >> 4) * 16;
    const uint32_t bAddr = sbase + BOFF
        + (uint32_t)(warpN * 64 + (lane & 7) + ((lane >> 4) << 3)) * ROWB
        + (uint32_t)((lane >> 3) & 1) * 16;

    float acc[2][8][4];
    float vsum[2][2] = {{0.0f, 0.0f}, {0.0f, 0.0f}};
    float vmax[2][2] = {{-1e30f, -1e30f}, {-1e30f, -1e30f}};
    int   vidx[2][2] = {{-1, -1}, {-1, -1}};

    auto load_stage = [&](int t) {
        const int nc = t >> 3, kb = t & 7, st = t & 1;
        const uint32_t base = sbase + (uint32_t)st * STAGE;
        #pragma unroll
        for (int i = 0; i < 4; ++i) {
            int row = lrow + i * 32;
            uint32_t ad = base + (uint32_t)row * ROWB + lk8 * 16;
            const void* as = Ag + (size_t)row * DIM + kb * BK;
            CPASYNC16(ad, as);
            uint32_t bd = base + BOFF + (uint32_t)row * ROWB + lk8 * 16;
            const void* bs = Bg + (size_t)(nc * NCHUNK + row) * DIM + kb * BK;
            CPASYNC16(bd, bs);
        }
        asm volatile("cp.async.commit_group;" ::: "memory");
    };

    load_stage(0);

    for (int t = 0; t < NSTAGES_TOTAL; ++t) {
        const int st = t & 1;
        if ((t & 7) == 0) {
            #pragma unroll
            for (int mt = 0; mt < 2; ++mt)
                #pragma unroll
                for (int n8 = 0; n8 < 8; ++n8)
                    #pragma unroll
                    for (int j = 0; j < 4; ++j) acc[mt][n8][j] = 0.0f;
        }
        if (t + 1 < NSTAGES_TOTAL) {
            load_stage(t + 1);
            asm volatile("cp.async.wait_group 1;" ::: "memory");
        } else {
            asm volatile("cp.async.wait_group 0;" ::: "memory");
        }
        __syncthreads();

        const uint32_t aS = aAddr + (uint32_t)st * STAGE;
        const uint32_t bS = bAddr + (uint32_t)st * STAGE;
        #pragma unroll
        for (int kk = 0; kk < 4; ++kk) {
            uint32_t A0[4], A1[4];
            LDSM4(A0[0], A0[1], A0[2], A0[3], aS + kk * 32);
            LDSM4(A1[0], A1[1], A1[2], A1[3], aS + 16 * ROWB + kk * 32);
            uint32_t B[8][2];
            #pragma unroll
            for (int nt = 0; nt < 4; ++nt) {
                uint32_t r0, r1, r2, r3;
                LDSM4(r0, r1, r2, r3, bS + (uint32_t)nt * 16 * ROWB + kk * 32);
                B[2 * nt][0] = r0; B[2 * nt][1] = r1;
                B[2 * nt + 1][0] = r2; B[2 * nt + 1][1] = r3;
            }
            #pragma unroll
            for (int n8 = 0; n8 < 8; ++n8) {
                MMA16816(acc[0][n8], A0, B[n8]);
                MMA16816(acc[1][n8], A1, B[n8]);
            }
        }

        if ((t & 7) == 7) {
            // epilogue for this n-chunk: exp(20c - 20), argmax, mask padding
            const int ncBase = (t >> 3) * NCHUNK + warpN * 64;
            #pragma unroll
            for (int mt = 0; mt < 2; ++mt) {
                #pragma unroll
                for (int n8 = 0; n8 < 8; ++n8) {
                    #pragma unroll
                    for (int j = 0; j < 4; ++j) {
                        int cls = ncBase + n8 * 8 + (lane & 3) * 2 + (j & 1);
                        if (cls < NC) {
                            float v  = acc[mt][n8][j];           // cosine
                            int   rh = j >> 1;
                            if (v > vmax[mt][rh]) { vmax[mt][rh] = v; vidx[mt][rh] = cls; }
                            // exp(20v - 20) = 2^(28.8539*(v-1))
                            float tt = fmaf(v, 28.853900817779268f, -28.853900817779268f);
                            float fj = tt + 12582912.0f;         // rn-to-int magic
                            float fi = fj - 12582912.0f;
                            float rr = tt - fi;                  // [-0.5, 0.5]
                            int   ei = __float_as_int(fj);
                            int   sb = (ei + (127 - 0x4B400000)) << 23;   // bits of 2^n
                            float p  = fmaf(rr, 0.0096181291f, 0.055504109f);
                            p = fmaf(rr, p, 0.24022651f);
                            p = fmaf(rr, p, 0.69314718f);
                            p = fmaf(rr, p, 1.0f);
                            vsum[mt][rh] = fmaf(p, __int_as_float(sb), vsum[mt][rh]);
                        }
                    }
                }
            }
        }
        __syncthreads();
    }

    // reduce across quad lanes (cols), then across the 2 N-warps
    #pragma unroll
    for (int mt = 0; mt < 2; ++mt) {
        #pragma unroll
        for (int rh = 0; rh < 2; ++rh) {
            float s = vsum[mt][rh], m = vmax[mt][rh];
            int   ix = vidx[mt][rh];
            #pragma unroll
            for (int o = 1; o <= 2; o <<= 1) {
                float so = __shfl_xor_sync(0xffffffffu, s, o);
                float mo = __shfl_xor_sync(0xffffffffu, m, o);
                int   io = __shfl_xor_sync(0xffffffffu, ix, o);
                s += so;
                if (mo > m) { m = mo; ix = io; }
            }
            if ((lane & 3) == 0) {
                int row = warpM * 32 + mt * 16 + rh * 8 + (lane >> 2);
                s_sum[warpN][row] = s;
                s_max[warpN][row] = m;
                s_idx[warpN][row] = ix;
            }
        }
    }
    __syncthreads();

    if (tid < TMR) {
        float sum = s_sum[0][tid] + s_sum[1][tid];
        float m0 = s_max[0][tid], m1 = s_max[1][tid];
        int   ix = (m1 > m0) ? s_idx[1][tid] : s_idx[0][tid];
        int grow = mBase + tid;
        g_lse[grow]  = 20.0f + __logf(sum);
        g_corr[grow] = (ix == label[grow]) ? 1.0f : 0.0f;
    }
}

// ---------------------------------------------------------------------------
// final deterministic reduction
// ---------------------------------------------------------------------------
__global__ void final_kernel(float* __restrict__ out, int out_size) {
    int tid = threadIdx.x;
    float sl = 0.0f, sc = 0.0f;
    for (int i = tid; i < BS; i += 1024) {
        sl += g_lse[i] + g_ta[i];
        sc += g_corr[i];
    }
    #pragma unroll
    for (int o = 16; o > 0; o >>= 1) {
        sl += __shfl_xor_sync(0xffffffffu, sl, o);
        sc += __shfl_xor_sync(0xffffffffu, sc, o);
    }
    __shared__ float a1[32], a2[32];
    int w = tid >> 5, l = tid & 31;
    if (l == 0) { a1[w] = sl; a2[w] = sc; }
    __syncthreads();
    if (w == 0) {
        sl = a1[l];
        sc = a2[l];
        #pragma unroll
        for (int o = 16; o > 0; o >>= 1) {
            sl += __shfl_xor_sync(0xffffffffu, sl, o);
            sc += __shfl_xor_sync(0xffffffffu, sc, o);
        }
        if (tid == 0) {
            out[0] = sl * (1.0f / BS);
            if (out_size > 1) out[1] = sc * (1.0f / BS);
        }
    }
}

// ---------------------------------------------------------------------------
// host
// ---------------------------------------------------------------------------
extern "C" void kernel_launch(void* const* d_in, const int* in_sizes, int n_in,
                              void* d_out, int out_size) {
    const float* f     = (const float*)d_in[0];
    const float* w     = (const float*)d_in[1];
    const int*   label = (const int*)d_in[2];
    const int*   aux   = (const int*)d_in[3];
    (void)in_sizes; (void)n_in;

    static int configured = 0;
    if (!configured) {
        cudaFuncSetAttribute(gemm_fused,
                             cudaFuncAttributeMaxDynamicSharedMemorySize, DSMEM);
        configured = 1;
    }

    prep_f_kernel<<<BS, 128>>>(f);
    prep_w_kernel<<<NPADC, 128>>>(w);
    gather_kernel<<<BS, 192>>>(f, w, label, aux);
    gemm_fused<<<BS / TMR, 256, DSMEM>>>(label);
    final_kernel<<<1, 1024>>>((float*)d_out, out_size);
}

// round 4
// speedup vs baseline: 8.0793x; 1.0427x over previous
#include <cuda_runtime.h>
#include <cuda_bf16.h>
#include <math.h>
#include <stdint.h>

// ---------------------------------------------------------------------------
// problem constants
// ---------------------------------------------------------------------------
#define BS     16384
#define NC     2000
#define NPADC  2048
#define DIM    512
#define TMR    64               // M rows per CTA
#define NCHUNK 128              // classes per N chunk
#define BK     64               // K per k-block
#define ROWB   144              // padded smem row stride in bytes (72 bf16)
#define AKB    (64 * ROWB)      // 9216 bytes per A k-block
#define ATOT   (8 * AKB)        // 73728 (all of A resident)
#define BSTG   (128 * ROWB)     // 18432 per B stage
#define DSMEM  (ATOT + 2 * BSTG)   // 110592
#define NITER  128              // 16 n-chunks * 8 k-blocks

// ---------------------------------------------------------------------------
// device scratch (allocation-free)
// ---------------------------------------------------------------------------
__device__ float g_finv[BS];
__device__ float g_winv[NC];
__device__ float g_ta[BS];
__device__ float g_lse[BS];
__device__ float g_corr[BS];
__device__ __nv_bfloat16 g_fb[(size_t)BS * DIM];
__device__ __nv_bfloat16 g_wb[(size_t)NPADC * DIM];

// ---------------------------------------------------------------------------
// helpers
// ---------------------------------------------------------------------------
static __device__ __forceinline__ uint32_t sm2u(const void* p) {
    uint32_t a;
    asm("{ .reg .u64 t; cvta.to.shared.u64 t, %1; cvt.u32.u64 %0, t; }"
        : "=r"(a) : "l"(p));
    return a;
}

#define LDSM4(r0, r1, r2, r3, addr) \
    asm volatile("ldmatrix.sync.aligned.m8n8.x4.shared.b16 {%0,%1,%2,%3}, [%4];" \
                 : "=r"(r0), "=r"(r1), "=r"(r2), "=r"(r3) : "r"(addr))

#define MMA16816(d, a, b) \
    asm volatile("mma.sync.aligned.m16n8k16.row.col.f32.bf16.bf16.f32 " \
                 "{%0,%1,%2,%3}, {%4,%5,%6,%7}, {%8,%9}, {%0,%1,%2,%3};" \
                 : "+f"((d)[0]), "+f"((d)[1]), "+f"((d)[2]), "+f"((d)[3]) \
                 : "r"((a)[0]), "r"((a)[1]), "r"((a)[2]), "r"((a)[3]), \
                   "r"((b)[0]), "r"((b)[1]))

#define CPASYNC16(dst, src) \
    asm volatile("cp.async.cg.shared.global [%0], [%1], 16;" :: "r"(dst), "l"(src))

// ---------------------------------------------------------------------------
// prep: rownorm + bf16 convert.  f -> g_fb (scaled by 1/||f||), w -> g_wb
// ---------------------------------------------------------------------------
__global__ void prep_f_kernel(const float* __restrict__ x) {
    int row = blockIdx.x;
    const float4* p = reinterpret_cast<const float4*>(x + (size_t)row * DIM);
    float4 v = p[threadIdx.x];
    float s = v.x * v.x + v.y * v.y + v.z * v.z + v.w * v.w;
    #pragma unroll
    for (int o = 16; o > 0; o >>= 1) s += __shfl_xor_sync(0xffffffffu, s, o);
    __shared__ float sm[4];
    __shared__ float sinv;
    int warp = threadIdx.x >> 5;
    if ((threadIdx.x & 31) == 0) sm[warp] = s;
    __syncthreads();
    if (threadIdx.x == 0) {
        float t = sm[0] + sm[1] + sm[2] + sm[3];
        float inv = 1.0f / fmaxf(sqrtf(t), 1e-12f);
        g_finv[row] = inv;
        sinv = inv;
    }
    __syncthreads();
    float inv = sinv;
    __nv_bfloat162 h0 = __floats2bfloat162_rn(v.x * inv, v.y * inv);
    __nv_bfloat162 h1 = __floats2bfloat162_rn(v.z * inv, v.w * inv);
    __nv_bfloat162* dp = reinterpret_cast<__nv_bfloat162*>(
        g_fb + (size_t)row * DIM + threadIdx.x * 4);
    dp[0] = h0;
    dp[1] = h1;
}

__global__ void prep_w_kernel(const float* __restrict__ x) {
    int row = blockIdx.x;
    __nv_bfloat162* dp = reinterpret_cast<__nv_bfloat162*>(
        g_wb + (size_t)row * DIM + threadIdx.x * 4);
    if (row >= NC) {
        __nv_bfloat162 z = __floats2bfloat162_rn(0.0f, 0.0f);
        dp[0] = z; dp[1] = z;
        return;
    }
    const float4* p = reinterpret_cast<const float4*>(x + (size_t)row * DIM);
    float4 v = p[threadIdx.x];
    float s = v.x * v.x + v.y * v.y + v.z * v.z + v.w * v.w;
    #pragma unroll
    for (int o = 16; o > 0; o >>= 1) s += __shfl_xor_sync(0xffffffffu, s, o);
    __shared__ float sm[4];
    __shared__ float sinv;
    int warp = threadIdx.x >> 5;
    if ((threadIdx.x & 31) == 0) sm[warp] = s;
    __syncthreads();
    if (threadIdx.x == 0) {
        float t = sm[0] + sm[1] + sm[2] + sm[3];
        float inv = 1.0f / fmaxf(sqrtf(t), 1e-12f);
        g_winv[row] = inv;
        sinv = inv;
    }
    __syncthreads();
    float inv = sinv;
    __nv_bfloat162 h0 = __floats2bfloat162_rn(v.x * inv, v.y * inv);
    __nv_bfloat162 h1 = __floats2bfloat162_rn(v.z * inv, v.w * inv);
    dp[0] = h0;
    dp[1] = h1;
}

// ---------------------------------------------------------------------------
// per-row gathers (exact f32): g_ta = -0.95*tgt - 0.01*aux_sum
// ---------------------------------------------------------------------------
__global__ void gather_kernel(const float* __restrict__ f, const float* __restrict__ w,
                              const int* __restrict__ label, const int* __restrict__ aux) {
    int row  = blockIdx.x;
    int warp = threadIdx.x >> 5;
    int lane = threadIdx.x & 31;
    int cls  = (warp == 0) ? label[row] : aux[row * 5 + warp - 1];
    const float4* fr = reinterpret_cast<const float4*>(f + (size_t)row * DIM);
    const float4* wr = reinterpret_cast<const float4*>(w + (size_t)cls * DIM);
    float s = 0.0f;
    #pragma unroll
    for (int k = lane; k < DIM / 4; k += 32) {
        float4 a = fr[k], b = wr[k];
        s += a.x * b.x + a.y * b.y + a.z * b.z + a.w * b.w;
    }
    #pragma unroll
    for (int o = 16; o > 0; o >>= 1) s += __shfl_xor_sync(0xffffffffu, s, o);
    __shared__ float sm[6];
    if (lane == 0) sm[warp] = s * g_finv[row] * g_winv[cls] * 20.0f;
    __syncthreads();
    if (threadIdx.x == 0) {
        float tgt  = sm[0];
        float auxs = sm[1] + sm[2] + sm[3] + sm[4] + sm[5];
        g_ta[row] = -0.95f * tgt - 0.01f * auxs;
    }
}

// ---------------------------------------------------------------------------
// fused bf16 mma.sync GEMM + fixed-max softmax reduction.
// TMR=64 rows/CTA, grid=256 -> 2 CTAs per SM (single wave on 148 SMs).
// A (64x512) fully resident in smem; B double-buffered (128x64 per stage).
// 8 warps: 4(M, 16 rows) x 2(N, 64 cols).
// ---------------------------------------------------------------------------
__global__ void __launch_bounds__(256, 2)
gemm_fused(const int* __restrict__ label) {
    extern __shared__ char dsm[];
    __shared__ float s_sum[2][TMR];
    __shared__ float s_max[2][TMR];
    __shared__ int   s_idx[2][TMR];

    const int tid   = threadIdx.x;
    const int lane  = tid & 31;
    const int wid   = tid >> 5;
    const int warpM = wid & 3;     // rows warpM*16
    const int warpN = wid >> 2;    // cols warpN*64
    const uint32_t sbase = sm2u(dsm);
    const int mBase = blockIdx.x * TMR;

    // loader mapping: 8 threads per row (16B chunks), 32 rows per pass
    const int lrow = tid >> 3;     // 0..31
    const int lk8  = tid & 7;      // 16B chunk within 64-K block

    // ---- prologue: load ALL of A (8 k-blocks) + B stage 0, one group ----
    {
        const __nv_bfloat16* Ag = g_fb + (size_t)mBase * DIM;
        #pragma unroll
        for (int kb = 0; kb < 8; ++kb) {
            #pragma unroll
            for (int i = 0; i < 2; ++i) {
                int row = lrow + i * 32;
                uint32_t ad = sbase + kb * AKB + (uint32_t)row * ROWB + lk8 * 16;
                const void* as = Ag + (size_t)row * DIM + kb * BK + lk8 * 8;
                CPASYNC16(ad, as);
            }
        }
        const __nv_bfloat16* Bg = g_wb;   // nc=0, kb=0
        #pragma unroll
        for (int i = 0; i < 4; ++i) {
            int row = lrow + i * 32;
            uint32_t bd = sbase + ATOT + (uint32_t)row * ROWB + lk8 * 16;
            const void* bs = Bg + (size_t)row * DIM + lk8 * 8;
            CPASYNC16(bd, bs);
        }
        asm volatile("cp.async.commit_group;" ::: "memory");
    }

    // ldmatrix base addresses
    const uint32_t aAddr = sbase
        + (uint32_t)(warpM * 16 + (lane & 15)) * ROWB + (uint32_t)(lane >> 4) * 16;
    const uint32_t bAddr = sbase + ATOT
        + (uint32_t)(warpN * 64 + (lane & 7) + ((lane >> 4) << 3)) * ROWB
        + (uint32_t)((lane >> 3) & 1) * 16;

    float acc[8][4];
    float vsum[2] = {0.0f, 0.0f};
    float vmax[2] = {-1e30f, -1e30f};
    int   vidx[2] = {-1, -1};

    for (int t = 0; t < NITER; ++t) {
        const int st = t & 1;
        if ((t & 7) == 0) {
            #pragma unroll
            for (int n8 = 0; n8 < 8; ++n8)
                #pragma unroll
                for (int j = 0; j < 4; ++j) acc[n8][j] = 0.0f;
        }
        if (t + 1 < NITER) {
            // prefetch B stage for t+1
            const int tn = t + 1, nc = tn >> 3, kb = tn & 7, sn = tn & 1;
            const __nv_bfloat16* Bg = g_wb + (size_t)(nc * NCHUNK) * DIM + kb * BK;
            #pragma unroll
            for (int i = 0; i < 4; ++i) {
                int row = lrow + i * 32;
                uint32_t bd = sbase + ATOT + (uint32_t)sn * BSTG
                            + (uint32_t)row * ROWB + lk8 * 16;
                const void* bs = Bg + (size_t)row * DIM + lk8 * 8;
                CPASYNC16(bd, bs);
            }
            asm volatile("cp.async.commit_group;" ::: "memory");
            asm volatile("cp.async.wait_group 1;" ::: "memory");
        } else {
            asm volatile("cp.async.wait_group 0;" ::: "memory");
        }
        __syncthreads();

        const uint32_t aS = aAddr + (uint32_t)(t & 7) * AKB;
        const uint32_t bS = bAddr + (uint32_t)st * BSTG;
        #pragma unroll
        for (int kk = 0; kk < 4; ++kk) {
            uint32_t A0[4];
            LDSM4(A0[0], A0[1], A0[2], A0[3], aS + kk * 32);
            uint32_t B[8][2];
            #pragma unroll
            for (int nt = 0; nt < 4; ++nt) {
                uint32_t r0, r1, r2, r3;
                LDSM4(r0, r1, r2, r3, bS + (uint32_t)nt * 16 * ROWB + kk * 32);
                B[2 * nt][0] = r0; B[2 * nt][1] = r1;
                B[2 * nt + 1][0] = r2; B[2 * nt + 1][1] = r3;
            }
            #pragma unroll
            for (int n8 = 0; n8 < 8; ++n8) MMA16816(acc[n8], A0, B[n8]);
        }

        if ((t & 7) == 7) {
            // epilogue for this n-chunk: exp(20c - 20), argmax, mask padding
            const int ncBase = (t >> 3) * NCHUNK + warpN * 64;
            #pragma unroll
            for (int n8 = 0; n8 < 8; ++n8) {
                #pragma unroll
                for (int j = 0; j < 4; ++j) {
                    int cls = ncBase + n8 * 8 + (lane & 3) * 2 + (j & 1);
                    if (cls < NC) {
                        float v  = acc[n8][j];               // cosine
                        int   rh = j >> 1;
                        if (v > vmax[rh]) { vmax[rh] = v; vidx[rh] = cls; }
                        // exp(20v - 20) = 2^(28.8539*(v-1)); fixed max = 20
                        float tt = fmaf(v, 28.853900817779268f, -28.853900817779268f);
                        float fj = tt + 12582912.0f;          // rn-to-int magic
                        float fi = fj - 12582912.0f;
                        float rr = tt - fi;                   // [-0.5, 0.5]
                        int   ei = __float_as_int(fj);
                        int   sb = (ei + (127 - 0x4B400000)) << 23;   // bits of 2^n
                        float p  = fmaf(rr, 0.0096181291f, 0.055504109f);
                        p = fmaf(rr, p, 0.24022651f);
                        p = fmaf(rr, p, 0.69314718f);
                        p = fmaf(rr, p, 1.0f);
                        vsum[rh] = fmaf(p, __int_as_float(sb), vsum[rh]);
                    }
                }
            }
        }
        __syncthreads();
    }

    // reduce across quad lanes (cols), then across the 2 N-warps
    #pragma unroll
    for (int rh = 0; rh < 2; ++rh) {
        float s = vsum[rh], m = vmax[rh];
        int   ix = vidx[rh];
        #pragma unroll
        for (int o = 1; o <= 2; o <<= 1) {
            float so = __shfl_xor_sync(0xffffffffu, s, o);
            float mo = __shfl_xor_sync(0xffffffffu, m, o);
            int   io = __shfl_xor_sync(0xffffffffu, ix, o);
            s += so;
            if (mo > m) { m = mo; ix = io; }
        }
        if ((lane & 3) == 0) {
            int row = warpM * 16 + rh * 8 + (lane >> 2);
            s_sum[warpN][row] = s;
            s_max[warpN][row] = m;
            s_idx[warpN][row] = ix;
        }
    }
    __syncthreads();

    if (tid < TMR) {
        float sum = s_sum[0][tid] + s_sum[1][tid];
        float m0 = s_max[0][tid], m1 = s_max[1][tid];
        int   ix = (m1 > m0) ? s_idx[1][tid] : s_idx[0][tid];
        int grow = mBase + tid;
        g_lse[grow]  = 20.0f + __logf(sum);
        g_corr[grow] = (ix == label[grow]) ? 1.0f : 0.0f;
    }
}

// ---------------------------------------------------------------------------
// final deterministic reduction
// ---------------------------------------------------------------------------
__global__ void final_kernel(float* __restrict__ out, int out_size) {
    int tid = threadIdx.x;
    float sl = 0.0f, sc = 0.0f;
    for (int i = tid; i < BS; i += 1024) {
        sl += g_lse[i] + g_ta[i];
        sc += g_corr[i];
    }
    #pragma unroll
    for (int o = 16; o > 0; o >>= 1) {
        sl += __shfl_xor_sync(0xffffffffu, sl, o);
        sc += __shfl_xor_sync(0xffffffffu, sc, o);
    }
    __shared__ float a1[32], a2[32];
    int w = tid >> 5, l = tid & 31;
    if (l == 0) { a1[w] = sl; a2[w] = sc; }
    __syncthreads();
    if (w == 0) {
        sl = a1[l];
        sc = a2[l];
        #pragma unroll
        for (int o = 16; o > 0; o >>= 1) {
            sl += __shfl_xor_sync(0xffffffffu, sl, o);
            sc += __shfl_xor_sync(0xffffffffu, sc, o);
        }
        if (tid == 0) {
            out[0] = sl * (1.0f / BS);
            if (out_size > 1) out[1] = sc * (1.0f / BS);
        }
    }
}

// ---------------------------------------------------------------------------
// host
// ---------------------------------------------------------------------------
extern "C" void kernel_launch(void* const* d_in, const int* in_sizes, int n_in,
                              void* d_out, int out_size) {
    const float* f     = (const float*)d_in[0];
    const float* w     = (const float*)d_in[1];
    const int*   label = (const int*)d_in[2];
    const int*   aux   = (const int*)d_in[3];
    (void)in_sizes; (void)n_in;

    static int configured = 0;
    if (!configured) {
        cudaFuncSetAttribute(gemm_fused,
                             cudaFuncAttributeMaxDynamicSharedMemorySize, DSMEM);
        configured = 1;
    }

    prep_f_kernel<<<BS, 128>>>(f);
    prep_w_kernel<<<NPADC, 128>>>(w);
    gather_kernel<<<BS, 192>>>(f, w, label, aux);
    gemm_fused<<<BS / TMR, 256, DSMEM>>>(label);
    final_kernel<<<1, 1024>>>((float*)d_out, out_size);
}

// round 5
// speedup vs baseline: 8.5031x; 1.0524x over previous
#include <cuda_runtime.h>
#include <cuda_bf16.h>
#include <math.h>
#include <stdint.h>

// ---------------------------------------------------------------------------
// problem constants
// ---------------------------------------------------------------------------
#define BS     16384
#define NC     2000
#define NPADC  2048
#define DIM    512
#define TMR    64               // M rows per CTA
#define NCHUNK 128              // classes per N chunk
#define ROWB   144              // padded smem row stride (72 bf16)
#define ABLK   (64 * ROWB)      // 9216  : A 64 rows x 64 k
#define BBLK   (128 * ROWB)     // 18432 : B 128 rows x 64 k
#define SLOT   (2*ABLK + 2*BBLK)   // 55296 : one pair (128 K) of A+B
#define DSMEM  (2 * SLOT)       // 110592
#define NPAIR  64               // 16 n-chunks * 4 pairs (128 K each)

// ---------------------------------------------------------------------------
// device scratch (allocation-free)
// ---------------------------------------------------------------------------
__device__ float g_finv[BS];
__device__ float g_winv[NC];
__device__ float g_ta[BS];
__device__ float g_lse[BS];
__device__ float g_corr[BS];
__device__ __nv_bfloat16 g_fb[(size_t)BS * DIM];
__device__ __nv_bfloat16 g_wb[(size_t)NPADC * DIM];

// ---------------------------------------------------------------------------
// helpers
// ---------------------------------------------------------------------------
static __device__ __forceinline__ uint32_t sm2u(const void* p) {
    uint32_t a;
    asm("{ .reg .u64 t; cvta.to.shared.u64 t, %1; cvt.u32.u64 %0, t; }"
        : "=r"(a) : "l"(p));
    return a;
}

#define LDSM4(r0, r1, r2, r3, addr) \
    asm volatile("ldmatrix.sync.aligned.m8n8.x4.shared.b16 {%0,%1,%2,%3}, [%4];" \
                 : "=r"(r0), "=r"(r1), "=r"(r2), "=r"(r3) : "r"(addr))

#define MMA16816(d, a, b) \
    asm volatile("mma.sync.aligned.m16n8k16.row.col.f32.bf16.bf16.f32 " \
                 "{%0,%1,%2,%3}, {%4,%5,%6,%7}, {%8,%9}, {%0,%1,%2,%3};" \
                 : "+f"((d)[0]), "+f"((d)[1]), "+f"((d)[2]), "+f"((d)[3]) \
                 : "r"((a)[0]), "r"((a)[1]), "r"((a)[2]), "r"((a)[3]), \
                   "r"((b)[0]), "r"((b)[1]))

#define CPASYNC16(dst, src) \
    asm volatile("cp.async.cg.shared.global [%0], [%1], 16;" :: "r"(dst), "l"(src))

// ---------------------------------------------------------------------------
// prep: rownorm + bf16 convert.  f -> g_fb (scaled by 1/||f||), w -> g_wb
// ---------------------------------------------------------------------------
__global__ void prep_f_kernel(const float* __restrict__ x) {
    int row = blockIdx.x;
    const float4* p = reinterpret_cast<const float4*>(x + (size_t)row * DIM);
    float4 v = p[threadIdx.x];
    float s = v.x * v.x + v.y * v.y + v.z * v.z + v.w * v.w;
    #pragma unroll
    for (int o = 16; o > 0; o >>= 1) s += __shfl_xor_sync(0xffffffffu, s, o);
    __shared__ float sm[4];
    __shared__ float sinv;
    int warp = threadIdx.x >> 5;
    if ((threadIdx.x & 31) == 0) sm[warp] = s;
    __syncthreads();
    if (threadIdx.x == 0) {
        float t = sm[0] + sm[1] + sm[2] + sm[3];
        float inv = 1.0f / fmaxf(sqrtf(t), 1e-12f);
        g_finv[row] = inv;
        sinv = inv;
    }
    __syncthreads();
    float inv = sinv;
    __nv_bfloat162 h0 = __floats2bfloat162_rn(v.x * inv, v.y * inv);
    __nv_bfloat162 h1 = __floats2bfloat162_rn(v.z * inv, v.w * inv);
    __nv_bfloat162* dp = reinterpret_cast<__nv_bfloat162*>(
        g_fb + (size_t)row * DIM + threadIdx.x * 4);
    dp[0] = h0;
    dp[1] = h1;
}

__global__ void prep_w_kernel(const float* __restrict__ x) {
    int row = blockIdx.x;
    __nv_bfloat162* dp = reinterpret_cast<__nv_bfloat162*>(
        g_wb + (size_t)row * DIM + threadIdx.x * 4);
    if (row >= NC) {
        __nv_bfloat162 z = __floats2bfloat162_rn(0.0f, 0.0f);
        dp[0] = z; dp[1] = z;
        return;
    }
    const float4* p = reinterpret_cast<const float4*>(x + (size_t)row * DIM);
    float4 v = p[threadIdx.x];
    float s = v.x * v.x + v.y * v.y + v.z * v.z + v.w * v.w;
    #pragma unroll
    for (int o = 16; o > 0; o >>= 1) s += __shfl_xor_sync(0xffffffffu, s, o);
    __shared__ float sm[4];
    __shared__ float sinv;
    int warp = threadIdx.x >> 5;
    if ((threadIdx.x & 31) == 0) sm[warp] = s;
    __syncthreads();
    if (threadIdx.x == 0) {
        float t = sm[0] + sm[1] + sm[2] + sm[3];
        float inv = 1.0f / fmaxf(sqrtf(t), 1e-12f);
        g_winv[row] = inv;
        sinv = inv;
    }
    __syncthreads();
    float inv = sinv;
    __nv_bfloat162 h0 = __floats2bfloat162_rn(v.x * inv, v.y * inv);
    __nv_bfloat162 h1 = __floats2bfloat162_rn(v.z * inv, v.w * inv);
    dp[0] = h0;
    dp[1] = h1;
}

// ---------------------------------------------------------------------------
// per-row gathers (exact f32): g_ta = -0.95*tgt - 0.01*aux_sum
// ---------------------------------------------------------------------------
__global__ void gather_kernel(const float* __restrict__ f, const float* __restrict__ w,
                              const int* __restrict__ label, const int* __restrict__ aux) {
    int row  = blockIdx.x;
    int warp = threadIdx.x >> 5;
    int lane = threadIdx.x & 31;
    int cls  = (warp == 0) ? label[row] : aux[row * 5 + warp - 1];
    const float4* fr = reinterpret_cast<const float4*>(f + (size_t)row * DIM);
    const float4* wr = reinterpret_cast<const float4*>(w + (size_t)cls * DIM);
    float s = 0.0f;
    #pragma unroll
    for (int k = lane; k < DIM / 4; k += 32) {
        float4 a = fr[k], b = wr[k];
        s += a.x * b.x + a.y * b.y + a.z * b.z + a.w * b.w;
    }
    #pragma unroll
    for (int o = 16; o > 0; o >>= 1) s += __shfl_xor_sync(0xffffffffu, s, o);
    __shared__ float sm[6];
    if (lane == 0) sm[warp] = s * g_finv[row] * g_winv[cls] * 20.0f;
    __syncthreads();
    if (threadIdx.x == 0) {
        float tgt  = sm[0];
        float auxs = sm[1] + sm[2] + sm[3] + sm[4] + sm[5];
        g_ta[row] = -0.95f * tgt - 0.01f * auxs;
    }
}

// ---------------------------------------------------------------------------
// fused bf16 mma.sync GEMM + fixed-max softmax reduction.
// TMR=64 rows/CTA, grid=256 -> 2 CTAs/SM.  Pair pipeline: each pair stages
// A(64x128) + B(128x128), one wait_group + one __syncthreads per pair (64
// total).  Warps: 2(M, 32 rows) x 4(N, 32 cols), warp tile 32x32.
// ---------------------------------------------------------------------------
__global__ void __launch_bounds__(256, 2)
gemm_fused(const int* __restrict__ label) {
    extern __shared__ char dsm[];
    // final-reduction arrays aliased into the (then-dead) pipeline buffer
    float* s_sum = reinterpret_cast<float*>(dsm);            // [4][64]
    float* s_max = reinterpret_cast<float*>(dsm + 1024);     // [4][64]
    int*   s_idx = reinterpret_cast<int*>(dsm + 2048);       // [4][64]

    const int tid   = threadIdx.x;
    const int lane  = tid & 31;
    const int wid   = tid >> 5;
    const int warpM = wid & 1;     // rows warpM*32
    const int warpN = wid >> 1;    // cols warpN*32
    const uint32_t sbase = sm2u(dsm);
    const int mBase = blockIdx.x * TMR;

    // ---- pair loader: A(2 k-blocks) + B(2 k-blocks), one commit group ----
    auto load_pair = [&](int p) {
        const int nc = p >> 2, kp = p & 3, slot = p & 1;
        const uint32_t sb = sbase + (uint32_t)slot * SLOT;
        const __nv_bfloat16* Asrc = g_fb + (size_t)mBase * DIM + kp * 128;
        const __nv_bfloat16* Bsrc = g_wb + (size_t)(nc * NCHUNK) * DIM + kp * 128;
        #pragma unroll
        for (int b = 0; b < 2; ++b) {
            #pragma unroll
            for (int i = 0; i < 2; ++i) {          // A: 512 chunks per block
                int ch = tid + 256 * i;
                int row = ch >> 3, c8 = ch & 7;
                CPASYNC16(sb + b * ABLK + (uint32_t)row * ROWB + c8 * 16,
                          Asrc + (size_t)row * DIM + b * 64 + c8 * 8);
            }
            #pragma unroll
            for (int i = 0; i < 4; ++i) {          // B: 1024 chunks per block
                int ch = tid + 256 * i;
                int row = ch >> 3, c8 = ch & 7;
                CPASYNC16(sb + 2 * ABLK + b * BBLK + (uint32_t)row * ROWB + c8 * 16,
                          Bsrc + (size_t)row * DIM + b * 64 + c8 * 8);
            }
        }
        asm volatile("cp.async.commit_group;" ::: "memory");
    };

    // ldmatrix intra-tile offsets
    const uint32_t aoff = (uint32_t)(warpM * 32 + (lane & 15)) * ROWB
                        + (uint32_t)(lane >> 4) * 16;
    const uint32_t boff = (uint32_t)(warpN * 32 + (lane & 7) + ((lane >> 4) << 3)) * ROWB
                        + (uint32_t)((lane >> 3) & 1) * 16;

    float acc[2][4][4];
    float vsum[2][2] = {{0.0f, 0.0f}, {0.0f, 0.0f}};
    float vmax[2][2] = {{-1e30f, -1e30f}, {-1e30f, -1e30f}};
    int   vidx[2][2] = {{-1, -1}, {-1, -1}};

    load_pair(0);

    for (int p = 0; p < NPAIR; ++p) {
        asm volatile("cp.async.wait_group 0;" ::: "memory");
        __syncthreads();                        // data visible; slot (p+1)&1 free
        if (p + 1 < NPAIR) load_pair(p + 1);

        if ((p & 3) == 0) {
            #pragma unroll
            for (int mt = 0; mt < 2; ++mt)
                #pragma unroll
                for (int n8 = 0; n8 < 4; ++n8)
                    #pragma unroll
                    for (int j = 0; j < 4; ++j) acc[mt][n8][j] = 0.0f;
        }

        const uint32_t sb = sbase + (uint32_t)(p & 1) * SLOT;
        #pragma unroll
        for (int b = 0; b < 2; ++b) {
            const uint32_t aS = sb + b * ABLK + aoff;
            const uint32_t bS = sb + 2 * ABLK + b * BBLK + boff;
            #pragma unroll
            for (int kk = 0; kk < 4; ++kk) {
                uint32_t A0[4], A1[4];
                LDSM4(A0[0], A0[1], A0[2], A0[3], aS + kk * 32);
                LDSM4(A1[0], A1[1], A1[2], A1[3], aS + 16 * ROWB + kk * 32);
                uint32_t B[4][2];
                {
                    uint32_t r0, r1, r2, r3;
                    LDSM4(r0, r1, r2, r3, bS + kk * 32);
                    B[0][0] = r0; B[0][1] = r1; B[1][0] = r2; B[1][1] = r3;
                    LDSM4(r0, r1, r2, r3, bS + 16 * ROWB + kk * 32);
                    B[2][0] = r0; B[2][1] = r1; B[3][0] = r2; B[3][1] = r3;
                }
                #pragma unroll
                for (int n8 = 0; n8 < 4; ++n8) {
                    MMA16816(acc[0][n8], A0, B[n8]);
                    MMA16816(acc[1][n8], A1, B[n8]);
                }
            }
        }

        if ((p & 3) == 3) {
            // epilogue for n-chunk: exp(20c - 20), argmax, mask padding
            const int ncBase = (p >> 2) * NCHUNK + warpN * 32;
            #pragma unroll
            for (int mt = 0; mt < 2; ++mt) {
                #pragma unroll
                for (int n8 = 0; n8 < 4; ++n8) {
                    #pragma unroll
                    for (int j = 0; j < 4; ++j) {
                        int cls = ncBase + n8 * 8 + (lane & 3) * 2 + (j & 1);
                        if (cls < NC) {
                            float v  = acc[mt][n8][j];       // cosine
                            int   rh = j >> 1;
                            if (v > vmax[mt][rh]) { vmax[mt][rh] = v; vidx[mt][rh] = cls; }
                            // exp(20v - 20) = 2^(28.8539*(v-1)); fixed max = 20
                            float tt = fmaf(v, 28.853900817779268f, -28.853900817779268f);
                            float fj = tt + 12582912.0f;      // rn-to-int magic
                            float fi = fj - 12582912.0f;
                            float rr = tt - fi;               // [-0.5, 0.5]
                            int   ei = __float_as_int(fj);
                            int   sb2 = (ei + (127 - 0x4B400000)) << 23;  // 2^n bits
                            float q  = fmaf(rr, 0.0096181291f, 0.055504109f);
                            q = fmaf(rr, q, 0.24022651f);
                            q = fmaf(rr, q, 0.69314718f);
                            q = fmaf(rr, q, 1.0f);
                            vsum[mt][rh] = fmaf(q, __int_as_float(sb2), vsum[mt][rh]);
                        }
                    }
                }
            }
        }
    }
    __syncthreads();   // pipeline buffer dead; reuse for reduction

    // reduce across quad lanes (cols within warp), write per-N-warp partials
    #pragma unroll
    for (int mt = 0; mt < 2; ++mt) {
        #pragma unroll
        for (int rh = 0; rh < 2; ++rh) {
            float s = vsum[mt][rh], m = vmax[mt][rh];
            int   ix = vidx[mt][rh];
            #pragma unroll
            for (int o = 1; o <= 2; o <<= 1) {
                float so = __shfl_xor_sync(0xffffffffu, s, o);
                float mo = __shfl_xor_sync(0xffffffffu, m, o);
                int   io = __shfl_xor_sync(0xffffffffu, ix, o);
                s += so;
                if (mo > m) { m = mo; ix = io; }
            }
            if ((lane & 3) == 0) {
                int row = warpM * 32 + mt * 16 + rh * 8 + (lane >> 2);
                s_sum[warpN * TMR + row] = s;
                s_max[warpN * TMR + row] = m;
                s_idx[warpN * TMR + row] = ix;
            }
        }
    }
    __syncthreads();

    if (tid < TMR) {
        float sum = 0.0f, m = -1e30f;
        int   ix = -1;
        #pragma unroll
        for (int wn = 0; wn < 4; ++wn) {
            sum += s_sum[wn * TMR + tid];
            float mw = s_max[wn * TMR + tid];
            if (mw > m) { m = mw; ix = s_idx[wn * TMR + tid]; }
        }
        int grow = mBase + tid;
        g_lse[grow]  = 20.0f + __logf(sum);
        g_corr[grow] = (ix == label[grow]) ? 1.0f : 0.0f;
    }
}

// ---------------------------------------------------------------------------
// final deterministic reduction
// ---------------------------------------------------------------------------
__global__ void final_kernel(float* __restrict__ out, int out_size) {
    int tid = threadIdx.x;
    float sl = 0.0f, sc = 0.0f;
    for (int i = tid; i < BS; i += 1024) {
        sl += g_lse[i] + g_ta[i];
        sc += g_corr[i];
    }
    #pragma unroll
    for (int o = 16; o > 0; o >>= 1) {
        sl += __shfl_xor_sync(0xffffffffu, sl, o);
        sc += __shfl_xor_sync(0xffffffffu, sc, o);
    }
    __shared__ float a1[32], a2[32];
    int w = tid >> 5, l = tid & 31;
    if (l == 0) { a1[w] = sl; a2[w] = sc; }
    __syncthreads();
    if (w == 0) {
        sl = a1[l];
        sc = a2[l];
        #pragma unroll
        for (int o = 16; o > 0; o >>= 1) {
            sl += __shfl_xor_sync(0xffffffffu, sl, o);
            sc += __shfl_xor_sync(0xffffffffu, sc, o);
        }
        if (tid == 0) {
            out[0] = sl * (1.0f / BS);
            if (out_size > 1) out[1] = sc * (1.0f / BS);
        }
    }
}

// ---------------------------------------------------------------------------
// host
// ---------------------------------------------------------------------------
extern "C" void kernel_launch(void* const* d_in, const int* in_sizes, int n_in,
                              void* d_out, int out_size) {
    const float* f     = (const float*)d_in[0];
    const float* w     = (const float*)d_in[1];
    const int*   label = (const int*)d_in[2];
    const int*   aux   = (const int*)d_in[3];
    (void)in_sizes; (void)n_in;

    static int configured = 0;
    if (!configured) {
        cudaFuncSetAttribute(gemm_fused,
                             cudaFuncAttributeMaxDynamicSharedMemorySize, DSMEM);
        configured = 1;
    }

    prep_f_kernel<<<BS, 128>>>(f);
    prep_w_kernel<<<NPADC, 128>>>(w);
    gather_kernel<<<BS, 192>>>(f, w, label, aux);
    gemm_fused<<<BS / TMR, 256, DSMEM>>>(label);
    final_kernel<<<1, 1024>>>((float*)d_out, out_size);
}

// round 6
// speedup vs baseline: 8.7603x; 1.0303x over previous
#include <cuda_runtime.h>
#include <cuda_bf16.h>
#include <math.h>
#include <stdint.h>

// ---------------------------------------------------------------------------
// problem constants
// ---------------------------------------------------------------------------
#define BS     16384
#define NC     2000
#define NPADC  2048
#define DIM    512
#define TMR    128              // M rows per CTA
#define NCH    256              // classes per N chunk
#define BK     64               // K per stage
#define ROWB   144              // padded smem row stride (72 bf16)
#define ABLK   (128 * ROWB)     // 18432
#define BBLK   (256 * ROWB)     // 36864
#define STG    (ABLK + BBLK)    // 55296
#define NSTG   3
#define DSMEM  (NSTG * STG)     // 165888
#define NITER  64               // 8 n-chunks * 8 k-blocks

// ---------------------------------------------------------------------------
// device scratch (allocation-free)
// ---------------------------------------------------------------------------
__device__ float g_finv[BS];
__device__ float g_winv[NC];
__device__ float g_ta[BS];
__device__ float g_lse[BS];
__device__ float g_corr[BS];
__device__ __nv_bfloat16 g_fb[(size_t)BS * DIM];
__device__ __nv_bfloat16 g_wb[(size_t)NPADC * DIM];

// ---------------------------------------------------------------------------
// helpers
// ---------------------------------------------------------------------------
static __device__ __forceinline__ uint32_t sm2u(const void* p) {
    uint32_t a;
    asm("{ .reg .u64 t; cvta.to.shared.u64 t, %1; cvt.u32.u64 %0, t; }"
        : "=r"(a) : "l"(p));
    return a;
}

#define LDSM4(r0, r1, r2, r3, addr) \
    asm volatile("ldmatrix.sync.aligned.m8n8.x4.shared.b16 {%0,%1,%2,%3}, [%4];" \
                 : "=r"(r0), "=r"(r1), "=r"(r2), "=r"(r3) : "r"(addr))

#define MMA16816(d, a, b) \
    asm volatile("mma.sync.aligned.m16n8k16.row.col.f32.bf16.bf16.f32 " \
                 "{%0,%1,%2,%3}, {%4,%5,%6,%7}, {%8,%9}, {%0,%1,%2,%3};" \
                 : "+f"((d)[0]), "+f"((d)[1]), "+f"((d)[2]), "+f"((d)[3]) \
                 : "r"((a)[0]), "r"((a)[1]), "r"((a)[2]), "r"((a)[3]), \
                   "r"((b)[0]), "r"((b)[1]))

#define CPASYNC16(dst, src) \
    asm volatile("cp.async.cg.shared.global [%0], [%1], 16;" :: "r"(dst), "l"(src))

// ---------------------------------------------------------------------------
// prep: rownorm + bf16 convert.  f -> g_fb (scaled by 1/||f||), w -> g_wb
// ---------------------------------------------------------------------------
__global__ void prep_f_kernel(const float* __restrict__ x) {
    int row = blockIdx.x;
    const float4* p = reinterpret_cast<const float4*>(x + (size_t)row * DIM);
    float4 v = p[threadIdx.x];
    float s = v.x * v.x + v.y * v.y + v.z * v.z + v.w * v.w;
    #pragma unroll
    for (int o = 16; o > 0; o >>= 1) s += __shfl_xor_sync(0xffffffffu, s, o);
    __shared__ float sm[4];
    __shared__ float sinv;
    int warp = threadIdx.x >> 5;
    if ((threadIdx.x & 31) == 0) sm[warp] = s;
    __syncthreads();
    if (threadIdx.x == 0) {
        float t = sm[0] + sm[1] + sm[2] + sm[3];
        float inv = 1.0f / fmaxf(sqrtf(t), 1e-12f);
        g_finv[row] = inv;
        sinv = inv;
    }
    __syncthreads();
    float inv = sinv;
    __nv_bfloat162 h0 = __floats2bfloat162_rn(v.x * inv, v.y * inv);
    __nv_bfloat162 h1 = __floats2bfloat162_rn(v.z * inv, v.w * inv);
    __nv_bfloat162* dp = reinterpret_cast<__nv_bfloat162*>(
        g_fb + (size_t)row * DIM + threadIdx.x * 4);
    dp[0] = h0;
    dp[1] = h1;
}

__global__ void prep_w_kernel(const float* __restrict__ x) {
    int row = blockIdx.x;
    __nv_bfloat162* dp = reinterpret_cast<__nv_bfloat162*>(
        g_wb + (size_t)row * DIM + threadIdx.x * 4);
    if (row >= NC) {
        __nv_bfloat162 z = __floats2bfloat162_rn(0.0f, 0.0f);
        dp[0] = z; dp[1] = z;
        return;
    }
    const float4* p = reinterpret_cast<const float4*>(x + (size_t)row * DIM);
    float4 v = p[threadIdx.x];
    float s = v.x * v.x + v.y * v.y + v.z * v.z + v.w * v.w;
    #pragma unroll
    for (int o = 16; o > 0; o >>= 1) s += __shfl_xor_sync(0xffffffffu, s, o);
    __shared__ float sm[4];
    __shared__ float sinv;
    int warp = threadIdx.x >> 5;
    if ((threadIdx.x & 31) == 0) sm[warp] = s;
    __syncthreads();
    if (threadIdx.x == 0) {
        float t = sm[0] + sm[1] + sm[2] + sm[3];
        float inv = 1.0f / fmaxf(sqrtf(t), 1e-12f);
        g_winv[row] = inv;
        sinv = inv;
    }
    __syncthreads();
    float inv = sinv;
    __nv_bfloat162 h0 = __floats2bfloat162_rn(v.x * inv, v.y * inv);
    __nv_bfloat162 h1 = __floats2bfloat162_rn(v.z * inv, v.w * inv);
    dp[0] = h0;
    dp[1] = h1;
}

// ---------------------------------------------------------------------------
// per-row gathers (exact f32): g_ta = -0.95*tgt - 0.01*aux_sum
// ---------------------------------------------------------------------------
__global__ void gather_kernel(const float* __restrict__ f, const float* __restrict__ w,
                              const int* __restrict__ label, const int* __restrict__ aux) {
    int row  = blockIdx.x;
    int warp = threadIdx.x >> 5;
    int lane = threadIdx.x & 31;
    int cls  = (warp == 0) ? label[row] : aux[row * 5 + warp - 1];
    const float4* fr = reinterpret_cast<const float4*>(f + (size_t)row * DIM);
    const float4* wr = reinterpret_cast<const float4*>(w + (size_t)cls * DIM);
    float s = 0.0f;
    #pragma unroll
    for (int k = lane; k < DIM / 4; k += 32) {
        float4 a = fr[k], b = wr[k];
        s += a.x * b.x + a.y * b.y + a.z * b.z + a.w * b.w;
    }
    #pragma unroll
    for (int o = 16; o > 0; o >>= 1) s += __shfl_xor_sync(0xffffffffu, s, o);
    __shared__ float sm[6];
    if (lane == 0) sm[warp] = s * g_finv[row] * g_winv[cls] * 20.0f;
    __syncthreads();
    if (threadIdx.x == 0) {
        float tgt  = sm[0];
        float auxs = sm[1] + sm[2] + sm[3] + sm[4] + sm[5];
        g_ta[row] = -0.95f * tgt - 0.01f * auxs;
    }
}

// ---------------------------------------------------------------------------
// fused bf16 mma.sync GEMM + fixed-max softmax reduction.
// CTA tile 128(M) x 256(N), 8 warps = 2(M) x 4(N), warp tile 64x64.
// 3-stage cp.async pipeline of K64 blocks (A 128x64 + B 256x64 per stage).
// 1 CTA/SM, grid = 128.
// ---------------------------------------------------------------------------
__global__ void __launch_bounds__(256, 1)
gemm_fused(const int* __restrict__ label) {
    extern __shared__ char dsm[];
    // final-reduction arrays aliased into the (then-dead) pipeline buffer
    float* s_sum = reinterpret_cast<float*>(dsm);            // [4][128]
    float* s_max = reinterpret_cast<float*>(dsm + 2048);     // [4][128]
    int*   s_idx = reinterpret_cast<int*>(dsm + 4096);       // [4][128]

    const int tid   = threadIdx.x;
    const int lane  = tid & 31;
    const int wid   = tid >> 5;
    const int warpM = wid & 1;     // rows warpM*64
    const int warpN = wid >> 1;    // cols warpN*64
    const uint32_t sbase = sm2u(dsm);
    const int mBase = blockIdx.x * TMR;

    // ldmatrix intra-tile offsets
    const uint32_t aoff = (uint32_t)(warpM * 64 + (lane & 15)) * ROWB
                        + (uint32_t)(lane >> 4) * 16;
    const uint32_t boff = (uint32_t)(warpN * 64 + (lane & 7) + ((lane >> 4) << 3)) * ROWB
                        + (uint32_t)((lane >> 3) & 1) * 16;

    float acc[4][8][4];            // [mt][n8][j]
    float vsum[4][2];
    float vmax[4][2];
    int   vidx[4][2];
    #pragma unroll
    for (int mt = 0; mt < 4; ++mt)
        #pragma unroll
        for (int rh = 0; rh < 2; ++rh) {
            vsum[mt][rh] = 0.0f; vmax[mt][rh] = -1e30f; vidx[mt][rh] = -1;
        }

    // ---- stage loader: A(128x64) + B(256x64), one commit group ----
    auto load_stage = [&](int t, int slot) {
        const int nc = t >> 3, kb = t & 7;
        const uint32_t sb = sbase + (uint32_t)slot * STG;
        const __nv_bfloat16* Asrc = g_fb + (size_t)mBase * DIM + kb * BK;
        const __nv_bfloat16* Bsrc = g_wb + (size_t)(nc * NCH) * DIM + kb * BK;
        #pragma unroll
        for (int i = 0; i < 4; ++i) {          // A: 1024 chunks
            int ch = tid + 256 * i;
            int row = ch >> 3, c8 = ch & 7;
            CPASYNC16(sb + (uint32_t)row * ROWB + c8 * 16,
                      Asrc + (size_t)row * DIM + c8 * 8);
        }
        #pragma unroll
        for (int i = 0; i < 8; ++i) {          // B: 2048 chunks
            int ch = tid + 256 * i;
            int row = ch >> 3, c8 = ch & 7;
            CPASYNC16(sb + ABLK + (uint32_t)row * ROWB + c8 * 16,
                      Bsrc + (size_t)row * DIM + c8 * 8);
        }
        asm volatile("cp.async.commit_group;" ::: "memory");
    };

    load_stage(0, 0);
    load_stage(1, 1);

    int csSlot = 0, ldSlot = 2;
    for (int t = 0; t < NITER; ++t) {
        if (t + 1 < NITER) {
            asm volatile("cp.async.wait_group 1;" ::: "memory");
        } else {
            asm volatile("cp.async.wait_group 0;" ::: "memory");
        }
        __syncthreads();
        if (t + 2 < NITER) {
            load_stage(t + 2, ldSlot);
            if (++ldSlot == NSTG) ldSlot = 0;
        }

        if ((t & 7) == 0) {
            #pragma unroll
            for (int mt = 0; mt < 4; ++mt)
                #pragma unroll
                for (int n8 = 0; n8 < 8; ++n8)
                    #pragma unroll
                    for (int j = 0; j < 4; ++j) acc[mt][n8][j] = 0.0f;
        }

        const uint32_t sb = sbase + (uint32_t)csSlot * STG;
        if (++csSlot == NSTG) csSlot = 0;
        const uint32_t aS = sb + aoff;
        const uint32_t bS = sb + ABLK + boff;
        #pragma unroll
        for (int kk = 0; kk < 4; ++kk) {
            uint32_t Af[4][4];
            #pragma unroll
            for (int mt = 0; mt < 4; ++mt)
                LDSM4(Af[mt][0], Af[mt][1], Af[mt][2], Af[mt][3],
                      aS + (uint32_t)mt * 16 * ROWB + kk * 32);
            uint32_t Bf[8][2];
            #pragma unroll
            for (int nt = 0; nt < 4; ++nt) {
                uint32_t r0, r1, r2, r3;
                LDSM4(r0, r1, r2, r3, bS + (uint32_t)nt * 16 * ROWB + kk * 32);
                Bf[2 * nt][0] = r0;     Bf[2 * nt][1] = r1;
                Bf[2 * nt + 1][0] = r2; Bf[2 * nt + 1][1] = r3;
            }
            #pragma unroll
            for (int mt = 0; mt < 4; ++mt)
                #pragma unroll
                for (int n8 = 0; n8 < 8; ++n8)
                    MMA16816(acc[mt][n8], Af[mt], Bf[n8]);
        }

        if ((t & 7) == 7) {
            // epilogue for this n-chunk: exp(20c - 20), argmax, mask padding
            const int ncBase = (t >> 3) * NCH + warpN * 64;
            #pragma unroll
            for (int mt = 0; mt < 4; ++mt) {
                #pragma unroll
                for (int n8 = 0; n8 < 8; ++n8) {
                    #pragma unroll
                    for (int j = 0; j < 4; ++j) {
                        int cls = ncBase + n8 * 8 + (lane & 3) * 2 + (j & 1);
                        if (cls < NC) {
                            float v  = acc[mt][n8][j];       // cosine
                            int   rh = j >> 1;
                            if (v > vmax[mt][rh]) { vmax[mt][rh] = v; vidx[mt][rh] = cls; }
                            // exp(20v - 20) = 2^(28.8539*(v-1)); fixed max = 20
                            float tt = fmaf(v, 28.853900817779268f, -28.853900817779268f);
                            float fj = tt + 12582912.0f;      // rn-to-int magic
                            float fi = fj - 12582912.0f;
                            float rr = tt - fi;               // [-0.5, 0.5]
                            int   ei = __float_as_int(fj);
                            int   sb2 = (ei + (127 - 0x4B400000)) << 23;  // 2^n bits
                            float q  = fmaf(rr, 0.0096181291f, 0.055504109f);
                            q = fmaf(rr, q, 0.24022651f);
                            q = fmaf(rr, q, 0.69314718f);
                            q = fmaf(rr, q, 1.0f);
                            vsum[mt][rh] = fmaf(q, __int_as_float(sb2), vsum[mt][rh]);
                        }
                    }
                }
            }
        }
    }
    __syncthreads();   // pipeline buffer dead; reuse for reduction

    // reduce across quad lanes (cols within warp), write per-N-warp partials
    #pragma unroll
    for (int mt = 0; mt < 4; ++mt) {
        #pragma unroll
        for (int rh = 0; rh < 2; ++rh) {
            float s = vsum[mt][rh], m = vmax[mt][rh];
            int   ix = vidx[mt][rh];
            #pragma unroll
            for (int o = 1; o <= 2; o <<= 1) {
                float so = __shfl_xor_sync(0xffffffffu, s, o);
                float mo = __shfl_xor_sync(0xffffffffu, m, o);
                int   io = __shfl_xor_sync(0xffffffffu, ix, o);
                s += so;
                if (mo > m) { m = mo; ix = io; }
            }
            if ((lane & 3) == 0) {
                int row = warpM * 64 + mt * 16 + rh * 8 + (lane >> 2);
                s_sum[warpN * TMR + row] = s;
                s_max[warpN * TMR + row] = m;
                s_idx[warpN * TMR + row] = ix;
            }
        }
    }
    __syncthreads();

    if (tid < TMR) {
        float sum = 0.0f, m = -1e30f;
        int   ix = -1;
        #pragma unroll
        for (int wn = 0; wn < 4; ++wn) {
            sum += s_sum[wn * TMR + tid];
            float mw = s_max[wn * TMR + tid];
            if (mw > m) { m = mw; ix = s_idx[wn * TMR + tid]; }
        }
        int grow = mBase + tid;
        g_lse[grow]  = 20.0f + __logf(sum);
        g_corr[grow] = (ix == label[grow]) ? 1.0f : 0.0f;
    }
}

// ---------------------------------------------------------------------------
// final deterministic reduction
// ---------------------------------------------------------------------------
__global__ void final_kernel(float* __restrict__ out, int out_size) {
    int tid = threadIdx.x;
    float sl = 0.0f, sc = 0.0f;
    for (int i = tid; i < BS; i += 1024) {
        sl += g_lse[i] + g_ta[i];
        sc += g_corr[i];
    }
    #pragma unroll
    for (int o = 16; o > 0; o >>= 1) {
        sl += __shfl_xor_sync(0xffffffffu, sl, o);
        sc += __shfl_xor_sync(0xffffffffu, sc, o);
    }
    __shared__ float a1[32], a2[32];
    int w = tid >> 5, l = tid & 31;
    if (l == 0) { a1[w] = sl; a2[w] = sc; }
    __syncthreads();
    if (w == 0) {
        sl = a1[l];
        sc = a2[l];
        #pragma unroll
        for (int o = 16; o > 0; o >>= 1) {
            sl += __shfl_xor_sync(0xffffffffu, sl, o);
            sc += __shfl_xor_sync(0xffffffffu, sc, o);
        }
        if (tid == 0) {
            out[0] = sl * (1.0f / BS);
            if (out_size > 1) out[1] = sc * (1.0f / BS);
        }
    }
}

// ---------------------------------------------------------------------------
// host
// ---------------------------------------------------------------------------
extern "C" void kernel_launch(void* const* d_in, const int* in_sizes, int n_in,
                              void* d_out, int out_size) {
    const float* f     = (const float*)d_in[0];
    const float* w     = (const float*)d_in[1];
    const int*   label = (const int*)d_in[2];
    const int*   aux   = (const int*)d_in[3];
    (void)in_sizes; (void)n_in;

    static int configured = 0;
    if (!configured) {
        cudaFuncSetAttribute(gemm_fused,
                             cudaFuncAttributeMaxDynamicSharedMemorySize, DSMEM);
        configured = 1;
    }

    prep_f_kernel<<<BS, 128>>>(f);
    prep_w_kernel<<<NPADC, 128>>>(w);
    gather_kernel<<<BS, 192>>>(f, w, label, aux);
    gemm_fused<<<BS / TMR, 256, DSMEM>>>(label);
    final_kernel<<<1, 1024>>>((float*)d_out, out_size);
}

// round 7
// speedup vs baseline: 8.7710x; 1.0012x over previous
#include <cuda_runtime.h>
#include <cuda_bf16.h>
#include <math.h>
#include <stdint.h>

// ---------------------------------------------------------------------------
// problem constants
// ---------------------------------------------------------------------------
#define BS     16384
#define NC     2000
#define NPADC  2048
#define DIM    512
#define TMR    128              // M rows per CTA
#define NCH    256              // classes per N chunk
#define BK     64               // K per stage
#define ROWB   144              // padded smem row stride (72 bf16)
#define ABLK   (128 * ROWB)     // 18432
#define BBLK   (256 * ROWB)     // 36864
#define STG    (ABLK + BBLK)    // 55296
#define NSTG   3
#define DSMEM  (NSTG * STG)     // 165888
#define NITER  64               // 8 n-chunks * 8 k-blocks

// ---------------------------------------------------------------------------
// device scratch (allocation-free)
// ---------------------------------------------------------------------------
__device__ float g_finv[BS];
__device__ float g_winv[NC];
__device__ float g_ta[BS];
__device__ float g_lse[BS];
__device__ float g_corr[BS];
__device__ __nv_bfloat16 g_fb[(size_t)BS * DIM];
__device__ __nv_bfloat16 g_wb[(size_t)NPADC * DIM];

// ---------------------------------------------------------------------------
// helpers
// ---------------------------------------------------------------------------
static __device__ __forceinline__ uint32_t sm2u(const void* p) {
    uint32_t a;
    asm("{ .reg .u64 t; cvta.to.shared.u64 t, %1; cvt.u32.u64 %0, t; }"
        : "=r"(a) : "l"(p));
    return a;
}

#define LDSM4(r0, r1, r2, r3, addr) \
    asm volatile("ldmatrix.sync.aligned.m8n8.x4.shared.b16 {%0,%1,%2,%3}, [%4];" \
                 : "=r"(r0), "=r"(r1), "=r"(r2), "=r"(r3) : "r"(addr))

#define MMA16816(d, a, b) \
    asm volatile("mma.sync.aligned.m16n8k16.row.col.f32.bf16.bf16.f32 " \
                 "{%0,%1,%2,%3}, {%4,%5,%6,%7}, {%8,%9}, {%0,%1,%2,%3};" \
                 : "+f"((d)[0]), "+f"((d)[1]), "+f"((d)[2]), "+f"((d)[3]) \
                 : "r"((a)[0]), "r"((a)[1]), "r"((a)[2]), "r"((a)[3]), \
                   "r"((b)[0]), "r"((b)[1]))

#define CPASYNC16(dst, src) \
    asm volatile("cp.async.cg.shared.global [%0], [%1], 16;" :: "r"(dst), "l"(src))

// load one kk-slice of fragments (A: 4x LDSM4, B: 4x LDSM4)
static __device__ __forceinline__ void ld_frags(uint32_t aS, uint32_t bS, int kk,
                                                uint32_t Af[4][4], uint32_t Bf[8][2]) {
    #pragma unroll
    for (int mt = 0; mt < 4; ++mt)
        LDSM4(Af[mt][0], Af[mt][1], Af[mt][2], Af[mt][3],
              aS + (uint32_t)mt * 16 * ROWB + kk * 32);
    #pragma unroll
    for (int nt = 0; nt < 4; ++nt) {
        uint32_t r0, r1, r2, r3;
        LDSM4(r0, r1, r2, r3, bS + (uint32_t)nt * 16 * ROWB + kk * 32);
        Bf[2 * nt][0] = r0;     Bf[2 * nt][1] = r1;
        Bf[2 * nt + 1][0] = r2; Bf[2 * nt + 1][1] = r3;
    }
}

// ---------------------------------------------------------------------------
// prep: rownorm + bf16 convert.  f -> g_fb (scaled by 1/||f||), w -> g_wb
// ---------------------------------------------------------------------------
__global__ void prep_f_kernel(const float* __restrict__ x) {
    int row = blockIdx.x;
    const float4* p = reinterpret_cast<const float4*>(x + (size_t)row * DIM);
    float4 v = p[threadIdx.x];
    float s = v.x * v.x + v.y * v.y + v.z * v.z + v.w * v.w;
    #pragma unroll
    for (int o = 16; o > 0; o >>= 1) s += __shfl_xor_sync(0xffffffffu, s, o);
    __shared__ float sm[4];
    __shared__ float sinv;
    int warp = threadIdx.x >> 5;
    if ((threadIdx.x & 31) == 0) sm[warp] = s;
    __syncthreads();
    if (threadIdx.x == 0) {
        float t = sm[0] + sm[1] + sm[2] + sm[3];
        float inv = 1.0f / fmaxf(sqrtf(t), 1e-12f);
        g_finv[row] = inv;
        sinv = inv;
    }
    __syncthreads();
    float inv = sinv;
    __nv_bfloat162 h0 = __floats2bfloat162_rn(v.x * inv, v.y * inv);
    __nv_bfloat162 h1 = __floats2bfloat162_rn(v.z * inv, v.w * inv);
    __nv_bfloat162* dp = reinterpret_cast<__nv_bfloat162*>(
        g_fb + (size_t)row * DIM + threadIdx.x * 4);
    dp[0] = h0;
    dp[1] = h1;
}

__global__ void prep_w_kernel(const float* __restrict__ x) {
    int row = blockIdx.x;
    __nv_bfloat162* dp = reinterpret_cast<__nv_bfloat162*>(
        g_wb + (size_t)row * DIM + threadIdx.x * 4);
    if (row >= NC) {
        __nv_bfloat162 z = __floats2bfloat162_rn(0.0f, 0.0f);
        dp[0] = z; dp[1] = z;
        return;
    }
    const float4* p = reinterpret_cast<const float4*>(x + (size_t)row * DIM);
    float4 v = p[threadIdx.x];
    float s = v.x * v.x + v.y * v.y + v.z * v.z + v.w * v.w;
    #pragma unroll
    for (int o = 16; o > 0; o >>= 1) s += __shfl_xor_sync(0xffffffffu, s, o);
    __shared__ float sm[4];
    __shared__ float sinv;
    int warp = threadIdx.x >> 5;
    if ((threadIdx.x & 31) == 0) sm[warp] = s;
    __syncthreads();
    if (threadIdx.x == 0) {
        float t = sm[0] + sm[1] + sm[2] + sm[3];
        float inv = 1.0f / fmaxf(sqrtf(t), 1e-12f);
        g_winv[row] = inv;
        sinv = inv;
    }
    __syncthreads();
    float inv = sinv;
    __nv_bfloat162 h0 = __floats2bfloat162_rn(v.x * inv, v.y * inv);
    __nv_bfloat162 h1 = __floats2bfloat162_rn(v.z * inv, v.w * inv);
    dp[0] = h0;
    dp[1] = h1;
}

// ---------------------------------------------------------------------------
// per-row gathers (exact f32): g_ta = -0.95*tgt - 0.01*aux_sum
// ---------------------------------------------------------------------------
__global__ void gather_kernel(const float* __restrict__ f, const float* __restrict__ w,
                              const int* __restrict__ label, const int* __restrict__ aux) {
    int row  = blockIdx.x;
    int warp = threadIdx.x >> 5;
    int lane = threadIdx.x & 31;
    int cls  = (warp == 0) ? label[row] : aux[row * 5 + warp - 1];
    const float4* fr = reinterpret_cast<const float4*>(f + (size_t)row * DIM);
    const float4* wr = reinterpret_cast<const float4*>(w + (size_t)cls * DIM);
    float s = 0.0f;
    #pragma unroll
    for (int k = lane; k < DIM / 4; k += 32) {
        float4 a = fr[k], b = wr[k];
        s += a.x * b.x + a.y * b.y + a.z * b.z + a.w * b.w;
    }
    #pragma unroll
    for (int o = 16; o > 0; o >>= 1) s += __shfl_xor_sync(0xffffffffu, s, o);
    __shared__ float sm[6];
    if (lane == 0) sm[warp] = s * g_finv[row] * g_winv[cls] * 20.0f;
    __syncthreads();
    if (threadIdx.x == 0) {
        float tgt  = sm[0];
        float auxs = sm[1] + sm[2] + sm[3] + sm[4] + sm[5];
        g_ta[row] = -0.95f * tgt - 0.01f * auxs;
    }
}

// ---------------------------------------------------------------------------
// fused bf16 mma.sync GEMM + fixed-max softmax reduction.
// CTA tile 128(M) x 256(N), 8 warps = 2(M) x 4(N), warp tile 64x64.
// 3-stage cp.async pipeline; register-fragment double buffering so
// LDSM(kk+1) issues before the 32 MMAs of kk (latency fully hidden).
// ---------------------------------------------------------------------------
__global__ void __launch_bounds__(256, 1)
gemm_fused(const int* __restrict__ label) {
    extern __shared__ char dsm[];
    // final-reduction arrays aliased into the (then-dead) pipeline buffer
    float* s_sum = reinterpret_cast<float*>(dsm);            // [4][128]
    float* s_max = reinterpret_cast<float*>(dsm + 2048);     // [4][128]
    int*   s_idx = reinterpret_cast<int*>(dsm + 4096);       // [4][128]

    const int tid   = threadIdx.x;
    const int lane  = tid & 31;
    const int wid   = tid >> 5;
    const int warpM = wid & 1;     // rows warpM*64
    const int warpN = wid >> 1;    // cols warpN*64
    const uint32_t sbase = sm2u(dsm);
    const int mBase = blockIdx.x * TMR;

    // ldmatrix intra-tile offsets
    const uint32_t aoff = (uint32_t)(warpM * 64 + (lane & 15)) * ROWB
                        + (uint32_t)(lane >> 4) * 16;
    const uint32_t boff = (uint32_t)(warpN * 64 + (lane & 7) + ((lane >> 4) << 3)) * ROWB
                        + (uint32_t)((lane >> 3) & 1) * 16;

    float acc[4][8][4];            // [mt][n8][j]
    float vsum[4][2];
    float vmax[4][2];
    int   vidx[4][2];
    #pragma unroll
    for (int mt = 0; mt < 4; ++mt)
        #pragma unroll
        for (int rh = 0; rh < 2; ++rh) {
            vsum[mt][rh] = 0.0f; vmax[mt][rh] = -1e30f; vidx[mt][rh] = -1;
        }

    // ---- stage loader: A(128x64) + B(256x64), one commit group ----
    auto load_stage = [&](int t, int slot) {
        const int nc = t >> 3, kb = t & 7;
        const uint32_t sb = sbase + (uint32_t)slot * STG;
        const __nv_bfloat16* Asrc = g_fb + (size_t)mBase * DIM + kb * BK;
        const __nv_bfloat16* Bsrc = g_wb + (size_t)(nc * NCH) * DIM + kb * BK;
        #pragma unroll
        for (int i = 0; i < 4; ++i) {          // A: 1024 chunks
            int ch = tid + 256 * i;
            int row = ch >> 3, c8 = ch & 7;
            CPASYNC16(sb + (uint32_t)row * ROWB + c8 * 16,
                      Asrc + (size_t)row * DIM + c8 * 8);
        }
        #pragma unroll
        for (int i = 0; i < 8; ++i) {          // B: 2048 chunks
            int ch = tid + 256 * i;
            int row = ch >> 3, c8 = ch & 7;
            CPASYNC16(sb + ABLK + (uint32_t)row * ROWB + c8 * 16,
                      Bsrc + (size_t)row * DIM + c8 * 8);
        }
        asm volatile("cp.async.commit_group;" ::: "memory");
    };

    load_stage(0, 0);
    load_stage(1, 1);

    int csSlot = 0, ldSlot = 2;
    for (int t = 0; t < NITER; ++t) {
        if (t + 1 < NITER) {
            asm volatile("cp.async.wait_group 1;" ::: "memory");
        } else {
            asm volatile("cp.async.wait_group 0;" ::: "memory");
        }
        __syncthreads();
        if (t + 2 < NITER) {
            load_stage(t + 2, ldSlot);
            if (++ldSlot == NSTG) ldSlot = 0;
        }

        if ((t & 7) == 0) {
            #pragma unroll
            for (int mt = 0; mt < 4; ++mt)
                #pragma unroll
                for (int n8 = 0; n8 < 8; ++n8)
                    #pragma unroll
                    for (int j = 0; j < 4; ++j) acc[mt][n8][j] = 0.0f;
        }

        const uint32_t sb = sbase + (uint32_t)csSlot * STG;
        if (++csSlot == NSTG) csSlot = 0;
        const uint32_t aS = sb + aoff;
        const uint32_t bS = sb + ABLK + boff;

        // ---- software-pipelined fragments: LDSM(kk+1) before MMA(kk) ----
        uint32_t Af[2][4][4], Bf[2][8][2];
        ld_frags(aS, bS, 0, Af[0], Bf[0]);
        #pragma unroll
        for (int kk = 0; kk < 4; ++kk) {
            const int cur = kk & 1;
            if (kk < 3) ld_frags(aS, bS, kk + 1, Af[cur ^ 1], Bf[cur ^ 1]);
            #pragma unroll
            for (int mt = 0; mt < 4; ++mt)
                #pragma unroll
                for (int n8 = 0; n8 < 8; ++n8)
                    MMA16816(acc[mt][n8], Af[cur][mt], Bf[cur][n8]);
        }

        if ((t & 7) == 7) {
            // epilogue for this n-chunk: exp(20c - 20), argmax, mask padding
            const int ncBase = (t >> 3) * NCH + warpN * 64;
            #pragma unroll
            for (int mt = 0; mt < 4; ++mt) {
                #pragma unroll
                for (int n8 = 0; n8 < 8; ++n8) {
                    #pragma unroll
                    for (int j = 0; j < 4; ++j) {
                        int cls = ncBase + n8 * 8 + (lane & 3) * 2 + (j & 1);
                        if (cls < NC) {
                            float v  = acc[mt][n8][j];       // cosine
                            int   rh = j >> 1;
                            if (v > vmax[mt][rh]) { vmax[mt][rh] = v; vidx[mt][rh] = cls; }
                            // exp(20v - 20) = 2^(28.8539*(v-1)); fixed max = 20
                            float tt = fmaf(v, 28.853900817779268f, -28.853900817779268f);
                            float fj = tt + 12582912.0f;      // rn-to-int magic
                            float fi = fj - 12582912.0f;
                            float rr = tt - fi;               // [-0.5, 0.5]
                            int   ei = __float_as_int(fj);
                            int   sb2 = (ei + (127 - 0x4B400000)) << 23;  // 2^n bits
                            float q  = fmaf(rr, 0.0096181291f, 0.055504109f);
                            q = fmaf(rr, q, 0.24022651f);
                            q = fmaf(rr, q, 0.69314718f);
                            q = fmaf(rr, q, 1.0f);
                            vsum[mt][rh] = fmaf(q, __int_as_float(sb2), vsum[mt][rh]);
                        }
                    }
                }
            }
        }
    }
    __syncthreads();   // pipeline buffer dead; reuse for reduction

    // reduce across quad lanes (cols within warp), write per-N-warp partials
    #pragma unroll
    for (int mt = 0; mt < 4; ++mt) {
        #pragma unroll
        for (int rh = 0; rh < 2; ++rh) {
            float s = vsum[mt][rh], m = vmax[mt][rh];
            int   ix = vidx[mt][rh];
            #pragma unroll
            for (int o = 1; o <= 2; o <<= 1) {
                float so = __shfl_xor_sync(0xffffffffu, s, o);
                float mo = __shfl_xor_sync(0xffffffffu, m, o);
                int   io = __shfl_xor_sync(0xffffffffu, ix, o);
                s += so;
                if (mo > m) { m = mo; ix = io; }
            }
            if ((lane & 3) == 0) {
                int row = warpM * 64 + mt * 16 + rh * 8 + (lane >> 2);
                s_sum[warpN * TMR + row] = s;
                s_max[warpN * TMR + row] = m;
                s_idx[warpN * TMR + row] = ix;
            }
        }
    }
    __syncthreads();

    if (tid < TMR) {
        float sum = 0.0f, m = -1e30f;
        int   ix = -1;
        #pragma unroll
        for (int wn = 0; wn < 4; ++wn) {
            sum += s_sum[wn * TMR + tid];
            float mw = s_max[wn * TMR + tid];
            if (mw > m) { m = mw; ix = s_idx[wn * TMR + tid]; }
        }
        int grow = mBase + tid;
        g_lse[grow]  = 20.0f + __logf(sum);
        g_corr[grow] = (ix == label[grow]) ? 1.0f : 0.0f;
    }
}

// ---------------------------------------------------------------------------
// final deterministic reduction
// ---------------------------------------------------------------------------
__global__ void final_kernel(float* __restrict__ out, int out_size) {
    int tid = threadIdx.x;
    float sl = 0.0f, sc = 0.0f;
    for (int i = tid; i < BS; i += 1024) {
        sl += g_lse[i] + g_ta[i];
        sc += g_corr[i];
    }
    #pragma unroll
    for (int o = 16; o > 0; o >>= 1) {
        sl += __shfl_xor_sync(0xffffffffu, sl, o);
        sc += __shfl_xor_sync(0xffffffffu, sc, o);
    }
    __shared__ float a1[32], a2[32];
    int w = tid >> 5, l = tid & 31;
    if (l == 0) { a1[w] = sl; a2[w] = sc; }
    __syncthreads();
    if (w == 0) {
        sl = a1[l];
        sc = a2[l];
        #pragma unroll
        for (int o = 16; o > 0; o >>= 1) {
            sl += __shfl_xor_sync(0xffffffffu, sl, o);
            sc += __shfl_xor_sync(0xffffffffu, sc, o);
        }
        if (tid == 0) {
            out[0] = sl * (1.0f / BS);
            if (out_size > 1) out[1] = sc * (1.0f / BS);
        }
    }
}

// ---------------------------------------------------------------------------
// host
// ---------------------------------------------------------------------------
extern "C" void kernel_launch(void* const* d_in, const int* in_sizes, int n_in,
                              void* d_out, int out_size) {
    const float* f     = (const float*)d_in[0];
    const float* w     = (const float*)d_in[1];
    const int*   label = (const int*)d_in[2];
    const int*   aux   = (const int*)d_in[3];
    (void)in_sizes; (void)n_in;

    static int configured = 0;
    if (!configured) {
        cudaFuncSetAttribute(gemm_fused,
                             cudaFuncAttributeMaxDynamicSharedMemorySize, DSMEM);
        configured = 1;
    }

    prep_f_kernel<<<BS, 128>>>(f);
    prep_w_kernel<<<NPADC, 128>>>(w);
    gather_kernel<<<BS, 192>>>(f, w, label, aux);
    gemm_fused<<<BS / TMR, 256, DSMEM>>>(label);
    final_kernel<<<1, 1024>>>((float*)d_out, out_size);
}